// round 10
// baseline (speedup 1.0000x reference)
#include <cuda_runtime.h>

// StructuralLoss: SSIM(11x11 box, zero pad, channel-summed) over (16,3,512,512) f32.
// Single fused kernel, 32(rows)x64(cols) output tile, halo 42x76, stride 76.
// 4 moment maps in 51KB smem; __launch_bounds__(512,4) caps regs at 32 ->
// 64 warps/SM (occupancy is the validated binding constraint: R5 47% / R9 70%
// both scaled time ~linearly with warps). Phase 1: float2 loads AND float2 smem
// stores. Phase 2: vertical sliding 11-sum, 296 column tasks, register ring.
// Phase 3: 512 tasks of 4 outputs (float4 loads, window = smem cols x+1..x+11).
// Per-block partial -> g_part[]; ticketed last block reduces deterministically.

#define KW 11
#define PADW 5
#define TROWS 32
#define TCOLS 64
#define EXTY 42          // halo rows = TROWS + 10
#define STRIDE 76        // halo cols (float4-aligned stride)
#define NQ 4
#define NTHREADS 512
#define BATCH 16
#define CH 3
#define IMH 512
#define IMW 512
#define NBX (IMW / TCOLS)    // 8
#define NBY (IMH / TROWS)    // 16
#define NBLOCKS (BATCH * NBY * NBX)   // 2048
#define QSZ (EXTY * STRIDE)           // 3192 floats

__device__ double g_part[NBLOCKS];
__device__ unsigned int g_ticket;   // zero-init; reset by last block each call

__global__ __launch_bounds__(NTHREADS, 4)
void ssim_main_kernel(const float* __restrict__ pred, const float* __restrict__ gt,
                      float* __restrict__ out) {
    extern __shared__ float sm[];
    // q: 0=sum_x 1=sum_y 2=sum_(x^2+y^2) 3=sum_xy; each EXTY x STRIDE.

    const int b    = blockIdx.z;
    const int gy0  = blockIdx.y * TROWS - PADW;
    const int gx0m = blockIdx.x * TCOLS - PADW - 1;   // even -> float2 aligned
    const size_t plane = (size_t)IMH * IMW;
    const float* pb = pred + (size_t)b * CH * plane;
    const float* gb = gt   + (size_t)b * CH * plane;

    // ---- Phase 1: load halo, build channel-summed moment maps ----
    const bool interior = (gy0 >= 0) && (gx0m >= 0) &&
                          (gy0 + EXTY <= IMH) && (gx0m + STRIDE <= IMW);
    if (interior) {
        // 42 rows x 38 float2 pairs = 1596 tasks; float2 smem stores (cols 2j,2j+1).
        for (int i = threadIdx.x; i < EXTY * 38; i += NTHREADS) {
            const int ry = i / 38;
            const int j  = i - ry * 38;
            const size_t idx = (size_t)(gy0 + ry) * IMW + (gx0m + 2 * j);
            const float2 pA = *(const float2*)(pb + idx);
            const float2 pB = *(const float2*)(pb + idx + plane);
            const float2 pC = *(const float2*)(pb + idx + 2 * plane);
            const float2 qA = *(const float2*)(gb + idx);
            const float2 qB = *(const float2*)(gb + idx + plane);
            const float2 qC = *(const float2*)(gb + idx + 2 * plane);

            const int o0 = ry * STRIDE + 2 * j;   // even -> float2-aligned smem
            *(float2*)(sm + 0 * QSZ + o0) =
                make_float2(pA.x + pB.x + pC.x, pA.y + pB.y + pC.y);
            *(float2*)(sm + 1 * QSZ + o0) =
                make_float2(qA.x + qB.x + qC.x, qA.y + qB.y + qC.y);
            *(float2*)(sm + 2 * QSZ + o0) = make_float2(
                pA.x * pA.x + pB.x * pB.x + pC.x * pC.x +
                qA.x * qA.x + qB.x * qB.x + qC.x * qC.x,
                pA.y * pA.y + pB.y * pB.y + pC.y * pC.y +
                qA.y * qA.y + qB.y * qB.y + qC.y * qC.y);
            *(float2*)(sm + 3 * QSZ + o0) = make_float2(
                pA.x * qA.x + pB.x * qB.x + pC.x * qC.x,
                pA.y * qA.y + pB.y * qB.y + pC.y * qC.y);
        }
    } else {
        // Scalar boundary path: all 76 cols written (zero where out of image).
        for (int i = threadIdx.x; i < EXTY * STRIDE; i += NTHREADS) {
            const int ry = i / STRIDE;
            const int s  = i - ry * STRIDE;
            const int gy = gy0 + ry;
            const int gx = gx0m + s;
            float p0 = 0.f, p1 = 0.f, p2 = 0.f, q0 = 0.f, q1 = 0.f, q2 = 0.f;
            if ((unsigned)gy < IMH && (unsigned)gx < IMW) {
                const size_t idx = (size_t)gy * IMW + gx;
                p0 = pb[idx]; p1 = pb[idx + plane]; p2 = pb[idx + 2 * plane];
                q0 = gb[idx]; q1 = gb[idx + plane]; q2 = gb[idx + 2 * plane];
            }
            const int off = ry * STRIDE + s;
            sm[0 * QSZ + off] = p0 + p1 + p2;
            sm[1 * QSZ + off] = q0 + q1 + q2;
            sm[2 * QSZ + off] =
                p0 * p0 + p1 * p1 + p2 * p2 + q0 * q0 + q1 * q1 + q2 * q2;
            sm[3 * QSZ + off] = p0 * q0 + p1 * q1 + p2 * q2;
        }
    }
    __syncthreads();

    // ---- Phase 2: vertical sliding 11-sum, scalar columns 1..74, in place.
    // 4 quantities x 74 columns = 296 tasks; thread owns its column end-to-end.
    {
        const int t = threadIdx.x;
        if (t < NQ * 74) {
            const int q = t / 74;
            const int x = t - q * 74 + 1;            // cols 1..74
            float* a = sm + q * QSZ + x;
            float v[KW];
            float s = 0.f;
            #pragma unroll
            for (int k = 0; k < KW; k++) {
                v[k] = a[k * STRIDE];
                s += v[k];
            }
            #pragma unroll
            for (int y = 0; y < TROWS; y++) {
                float nxt = 0.f;
                if (y < TROWS - 1) nxt = a[(y + KW) * STRIDE];
                a[y * STRIDE] = s;              // colsum for output row y
                const int ri = y % KW;          // compile-time (unrolled)
                s += nxt - v[ri];
                v[ri] = nxt;
            }
        }
    }
    __syncthreads();

    // ---- Phase 3: horizontal sliding 11-sum via float4 loads + SSIM ----
    // Exactly 512 tasks: 32 rows x 16 segments of 4 outputs. Output x window is
    // smem cols [x+1, x+11]; thread reads cols [xb, xb+16), uses v[1..14].
    const int y  = threadIdx.x >> 4;            // 0..31
    const int xb = (threadIdx.x & 15) * 4;      // 0,4,...,60 (float4-aligned)

    const float invN   = 1.0f / 363.0f;   // N = C*K*K
    const float invNm1 = 1.0f / 362.0f;
    const float C1v = 0.01f * 0.01f;
    const float C2v = 0.03f * 0.03f;
    const float EPSv = 1e-8f;

    float acc = 0.f;
    {
        float w[NQ][4];
        #pragma unroll
        for (int q = 0; q < NQ; q++) {
            const float4* r4 = (const float4*)(sm + q * QSZ + y * STRIDE + xb);
            const float4 a0 = r4[0], a1 = r4[1], a2 = r4[2], a3 = r4[3];
            const float v[16] = {a0.x, a0.y, a0.z, a0.w, a1.x, a1.y, a1.z, a1.w,
                                 a2.x, a2.y, a2.z, a2.w, a3.x, a3.y, a3.z, a3.w};
            float s = 0.f;
            #pragma unroll
            for (int k = 1; k <= KW; k++) s += v[k];
            w[q][0] = s;
            #pragma unroll
            for (int i = 1; i < 4; i++) {
                s += v[i + KW] - v[i];
                w[q][i] = s;
            }
        }

        #pragma unroll
        for (int xi = 0; xi < 4; xi++) {
            const float sp = w[0][xi], sg = w[1][xi], sq = w[2][xi], sc = w[3][xi];
            const float mu_p = sp * invN;
            const float mu_g = sg * invN;
            const float varsum = (sq - sp * mu_p - sg * mu_g) * invNm1; // var_p+var_g
            const float cov    = (sc - sp * mu_g) * invN;
            const float num = (2.0f * mu_p * mu_g + C1v) * (2.0f * cov + C2v);
            const float den = (mu_p * mu_p + mu_g * mu_g + C1v) * (varsum + C2v);
            acc += __fdividef(num, den + EPSv);
        }
    }

    // ---- Block reduction -> per-block partial ----
    #pragma unroll
    for (int off = 16; off > 0; off >>= 1)
        acc += __shfl_down_sync(0xFFFFFFFFu, acc, off);

    __shared__ float warp_sums[NTHREADS / 32];
    __shared__ bool s_is_last;
    const int lane = threadIdx.x & 31;
    const int wid  = threadIdx.x >> 5;
    if (lane == 0) warp_sums[wid] = acc;
    __syncthreads();
    if (wid == 0) {
        float v = (lane < NTHREADS / 32) ? warp_sums[lane] : 0.f;
        #pragma unroll
        for (int off = 8; off > 0; off >>= 1)
            v += __shfl_down_sync(0xFFFFFFFFu, v, off);
        if (lane == 0) {
            const int bid = blockIdx.x + NBX * (blockIdx.y + NBY * blockIdx.z);
            g_part[bid] = (double)v;
            __threadfence();
            const unsigned int old = atomicAdd(&g_ticket, 1u);
            s_is_last = (old == NBLOCKS - 1);
        }
    }
    __syncthreads();

    // ---- Last block: deterministic final reduction + output + ticket reset ----
    if (s_is_last) {
        __shared__ double dsum[NTHREADS / 32];
        double v = 0.0;
        for (int i = threadIdx.x; i < NBLOCKS; i += NTHREADS) v += g_part[i];
        #pragma unroll
        for (int off = 16; off > 0; off >>= 1)
            v += __shfl_down_sync(0xFFFFFFFFu, v, off);
        if (lane == 0) dsum[wid] = v;
        __syncthreads();
        if (wid == 0) {
            double t = (lane < NTHREADS / 32) ? dsum[lane] : 0.0;
            #pragma unroll
            for (int off = 8; off > 0; off >>= 1)
                t += __shfl_down_sync(0xFFFFFFFFu, t, off);
            if (lane == 0) {
                const double npix = (double)BATCH * IMH * IMW;
                out[0] = (float)(1.0 - t / npix);
                g_ticket = 0;   // reset for next (graph-replayed) call
            }
        }
    }
}

extern "C" void kernel_launch(void* const* d_in, const int* in_sizes, int n_in,
                              void* d_out, int out_size) {
    const float* pred = (const float*)d_in[0];
    const float* gt   = (const float*)d_in[1];
    float* out = (float*)d_out;

    const int smem_bytes = NQ * QSZ * (int)sizeof(float);   // 51072
    cudaFuncSetAttribute(ssim_main_kernel,
                         cudaFuncAttributeMaxDynamicSharedMemorySize, smem_bytes);

    dim3 grid(NBX, NBY, BATCH);   // 8 x 16 x 16 = 2048 blocks
    ssim_main_kernel<<<grid, NTHREADS, smem_bytes>>>(pred, gt, out);
}

// round 12
// speedup vs baseline: 1.1834x; 1.1834x over previous
#include <cuda_runtime.h>

// StructuralLoss: SSIM(11x11 box, zero pad, channel-summed) over (16,3,512,512) f32.
// Single fused kernel, 32(rows)x64(cols) output tile, halo 42x76, stride 76.
// 4 moment maps in 51KB smem; __launch_bounds__(512,3) -> 48 warps/SM, regs ~40
// (validated optimum: 32w=53us, 48w=47us, 64w(spill)=56us). Phase 1: float2
// global loads AND float2 smem stores. Phase 2: vertical sliding 11-sum, 296
// column tasks, register ring, in place. Phase 3: 512 tasks of 4 outputs
// (float4 loads, window = smem cols x+1..x+11). Per-block partial -> g_part[];
// ticketed last block reduces deterministically.

#define KW 11
#define PADW 5
#define TROWS 32
#define TCOLS 64
#define EXTY 42          // halo rows = TROWS + 10
#define STRIDE 76        // halo cols (float4-aligned stride)
#define NQ 4
#define NTHREADS 512
#define BATCH 16
#define CH 3
#define IMH 512
#define IMW 512
#define NBX (IMW / TCOLS)    // 8
#define NBY (IMH / TROWS)    // 16
#define NBLOCKS (BATCH * NBY * NBX)   // 2048
#define QSZ (EXTY * STRIDE)           // 3192 floats

__device__ double g_part[NBLOCKS];
__device__ unsigned int g_ticket;   // zero-init; reset by last block each call

__global__ __launch_bounds__(NTHREADS, 3)
void ssim_main_kernel(const float* __restrict__ pred, const float* __restrict__ gt,
                      float* __restrict__ out) {
    extern __shared__ float sm[];
    // q: 0=sum_x 1=sum_y 2=sum_(x^2+y^2) 3=sum_xy; each EXTY x STRIDE.

    const int b    = blockIdx.z;
    const int gy0  = blockIdx.y * TROWS - PADW;
    const int gx0m = blockIdx.x * TCOLS - PADW - 1;   // even -> float2 aligned
    const size_t plane = (size_t)IMH * IMW;
    const float* pb = pred + (size_t)b * CH * plane;
    const float* gb = gt   + (size_t)b * CH * plane;

    // ---- Phase 1: load halo, build channel-summed moment maps ----
    const bool interior = (gy0 >= 0) && (gx0m >= 0) &&
                          (gy0 + EXTY <= IMH) && (gx0m + STRIDE <= IMW);
    if (interior) {
        // 42 rows x 38 float2 pairs = 1596 tasks; float2 smem stores (cols 2j,2j+1).
        for (int i = threadIdx.x; i < EXTY * 38; i += NTHREADS) {
            const int ry = i / 38;
            const int j  = i - ry * 38;
            const size_t idx = (size_t)(gy0 + ry) * IMW + (gx0m + 2 * j);
            const float2 pA = *(const float2*)(pb + idx);
            const float2 pB = *(const float2*)(pb + idx + plane);
            const float2 pC = *(const float2*)(pb + idx + 2 * plane);
            const float2 qA = *(const float2*)(gb + idx);
            const float2 qB = *(const float2*)(gb + idx + plane);
            const float2 qC = *(const float2*)(gb + idx + 2 * plane);

            const int o0 = ry * STRIDE + 2 * j;   // even -> float2-aligned smem
            *(float2*)(sm + 0 * QSZ + o0) =
                make_float2(pA.x + pB.x + pC.x, pA.y + pB.y + pC.y);
            *(float2*)(sm + 1 * QSZ + o0) =
                make_float2(qA.x + qB.x + qC.x, qA.y + qB.y + qC.y);
            *(float2*)(sm + 2 * QSZ + o0) = make_float2(
                pA.x * pA.x + pB.x * pB.x + pC.x * pC.x +
                qA.x * qA.x + qB.x * qB.x + qC.x * qC.x,
                pA.y * pA.y + pB.y * pB.y + pC.y * pC.y +
                qA.y * qA.y + qB.y * qB.y + qC.y * qC.y);
            *(float2*)(sm + 3 * QSZ + o0) = make_float2(
                pA.x * qA.x + pB.x * qB.x + pC.x * qC.x,
                pA.y * qA.y + pB.y * qB.y + pC.y * qC.y);
        }
    } else {
        // Scalar boundary path: all 76 cols written (zero where out of image).
        for (int i = threadIdx.x; i < EXTY * STRIDE; i += NTHREADS) {
            const int ry = i / STRIDE;
            const int s  = i - ry * STRIDE;
            const int gy = gy0 + ry;
            const int gx = gx0m + s;
            float p0 = 0.f, p1 = 0.f, p2 = 0.f, q0 = 0.f, q1 = 0.f, q2 = 0.f;
            if ((unsigned)gy < IMH && (unsigned)gx < IMW) {
                const size_t idx = (size_t)gy * IMW + gx;
                p0 = pb[idx]; p1 = pb[idx + plane]; p2 = pb[idx + 2 * plane];
                q0 = gb[idx]; q1 = gb[idx + plane]; q2 = gb[idx + 2 * plane];
            }
            const int off = ry * STRIDE + s;
            sm[0 * QSZ + off] = p0 + p1 + p2;
            sm[1 * QSZ + off] = q0 + q1 + q2;
            sm[2 * QSZ + off] =
                p0 * p0 + p1 * p1 + p2 * p2 + q0 * q0 + q1 * q1 + q2 * q2;
            sm[3 * QSZ + off] = p0 * q0 + p1 * q1 + p2 * q2;
        }
    }
    __syncthreads();

    // ---- Phase 2: vertical sliding 11-sum, scalar columns 1..74, in place.
    // 4 quantities x 74 columns = 296 tasks; thread owns its column end-to-end.
    {
        const int t = threadIdx.x;
        if (t < NQ * 74) {
            const int q = t / 74;
            const int x = t - q * 74 + 1;            // cols 1..74
            float* a = sm + q * QSZ + x;
            float v[KW];
            float s = 0.f;
            #pragma unroll
            for (int k = 0; k < KW; k++) {
                v[k] = a[k * STRIDE];
                s += v[k];
            }
            #pragma unroll
            for (int y = 0; y < TROWS; y++) {
                float nxt = 0.f;
                if (y < TROWS - 1) nxt = a[(y + KW) * STRIDE];
                a[y * STRIDE] = s;              // colsum for output row y
                const int ri = y % KW;          // compile-time (unrolled)
                s += nxt - v[ri];
                v[ri] = nxt;
            }
        }
    }
    __syncthreads();

    // ---- Phase 3: horizontal sliding 11-sum via float4 loads + SSIM ----
    // Exactly 512 tasks: 32 rows x 16 segments of 4 outputs. Output x window is
    // smem cols [x+1, x+11]; thread reads cols [xb, xb+16), uses v[1..14].
    const int y  = threadIdx.x >> 4;            // 0..31
    const int xb = (threadIdx.x & 15) * 4;      // 0,4,...,60 (float4-aligned)

    const float invN   = 1.0f / 363.0f;   // N = C*K*K
    const float invNm1 = 1.0f / 362.0f;
    const float C1v = 0.01f * 0.01f;
    const float C2v = 0.03f * 0.03f;
    const float EPSv = 1e-8f;

    float acc = 0.f;
    {
        float w[NQ][4];
        #pragma unroll
        for (int q = 0; q < NQ; q++) {
            const float4* r4 = (const float4*)(sm + q * QSZ + y * STRIDE + xb);
            const float4 a0 = r4[0], a1 = r4[1], a2 = r4[2], a3 = r4[3];
            const float v[16] = {a0.x, a0.y, a0.z, a0.w, a1.x, a1.y, a1.z, a1.w,
                                 a2.x, a2.y, a2.z, a2.w, a3.x, a3.y, a3.z, a3.w};
            float s = 0.f;
            #pragma unroll
            for (int k = 1; k <= KW; k++) s += v[k];
            w[q][0] = s;
            #pragma unroll
            for (int i = 1; i < 4; i++) {
                s += v[i + KW] - v[i];
                w[q][i] = s;
            }
        }

        #pragma unroll
        for (int xi = 0; xi < 4; xi++) {
            const float sp = w[0][xi], sg = w[1][xi], sq = w[2][xi], sc = w[3][xi];
            const float mu_p = sp * invN;
            const float mu_g = sg * invN;
            const float varsum = (sq - sp * mu_p - sg * mu_g) * invNm1; // var_p+var_g
            const float cov    = (sc - sp * mu_g) * invN;
            const float num = (2.0f * mu_p * mu_g + C1v) * (2.0f * cov + C2v);
            const float den = (mu_p * mu_p + mu_g * mu_g + C1v) * (varsum + C2v);
            acc += __fdividef(num, den + EPSv);
        }
    }

    // ---- Block reduction -> per-block partial ----
    #pragma unroll
    for (int off = 16; off > 0; off >>= 1)
        acc += __shfl_down_sync(0xFFFFFFFFu, acc, off);

    __shared__ float warp_sums[NTHREADS / 32];
    __shared__ bool s_is_last;
    const int lane = threadIdx.x & 31;
    const int wid  = threadIdx.x >> 5;
    if (lane == 0) warp_sums[wid] = acc;
    __syncthreads();
    if (wid == 0) {
        float v = (lane < NTHREADS / 32) ? warp_sums[lane] : 0.f;
        #pragma unroll
        for (int off = 8; off > 0; off >>= 1)
            v += __shfl_down_sync(0xFFFFFFFFu, v, off);
        if (lane == 0) {
            const int bid = blockIdx.x + NBX * (blockIdx.y + NBY * blockIdx.z);
            g_part[bid] = (double)v;
            __threadfence();
            const unsigned int old = atomicAdd(&g_ticket, 1u);
            s_is_last = (old == NBLOCKS - 1);
        }
    }
    __syncthreads();

    // ---- Last block: deterministic final reduction + output + ticket reset ----
    if (s_is_last) {
        __shared__ double dsum[NTHREADS / 32];
        double v = 0.0;
        for (int i = threadIdx.x; i < NBLOCKS; i += NTHREADS) v += g_part[i];
        #pragma unroll
        for (int off = 16; off > 0; off >>= 1)
            v += __shfl_down_sync(0xFFFFFFFFu, v, off);
        if (lane == 0) dsum[wid] = v;
        __syncthreads();
        if (wid == 0) {
            double t = (lane < NTHREADS / 32) ? dsum[lane] : 0.0;
            #pragma unroll
            for (int off = 8; off > 0; off >>= 1)
                t += __shfl_down_sync(0xFFFFFFFFu, t, off);
            if (lane == 0) {
                const double npix = (double)BATCH * IMH * IMW;
                out[0] = (float)(1.0 - t / npix);
                g_ticket = 0;   // reset for next (graph-replayed) call
            }
        }
    }
}

extern "C" void kernel_launch(void* const* d_in, const int* in_sizes, int n_in,
                              void* d_out, int out_size) {
    const float* pred = (const float*)d_in[0];
    const float* gt   = (const float*)d_in[1];
    float* out = (float*)d_out;

    const int smem_bytes = NQ * QSZ * (int)sizeof(float);   // 51072
    cudaFuncSetAttribute(ssim_main_kernel,
                         cudaFuncAttributeMaxDynamicSharedMemorySize, smem_bytes);

    dim3 grid(NBX, NBY, BATCH);   // 8 x 16 x 16 = 2048 blocks
    ssim_main_kernel<<<grid, NTHREADS, smem_bytes>>>(pred, gt, out);
}